// round 10
// baseline (speedup 1.0000x reference)
#include <cuda_runtime.h>

typedef unsigned long long ULL;

#define B_DIM 16
#define C_DIM 64
#define K_DIM 207
#define L_DIM 64
#define KL (K_DIM*L_DIM)      /* 13248 */
#define KK (K_DIM*K_DIM)      /* 42849 */
#define CIN 320

// scratch (allocation-free rule: __device__ globals)
__device__ float g_S[2*B_DIM*KK];                       // A0^2, A1^2 per batch (~5.5MB)
__device__ float g_t[(size_t)4*B_DIM*C_DIM*KL];         // A0x, S0x, A1x, S1x (~217MB)

// ---------------- f32x2 helpers (FFMA2 path, sm_100+) ----------------
__device__ __forceinline__ ULL pack2(float v) {
    ULL r; asm("mov.b64 %0, {%1, %1};" : "=l"(r) : "r"(__float_as_uint(v)));
    return r;
}
__device__ __forceinline__ ULL packxy(float a, float b) {
    ULL r; asm("mov.b64 %0, {%1, %2};" : "=l"(r) : "r"(__float_as_uint(a)), "r"(__float_as_uint(b)));
    return r;
}
__device__ __forceinline__ ULL fma2(ULL a, ULL b, ULL c) {
    ULL d; asm("fma.rn.f32x2 %0, %1, %2, %3;" : "=l"(d) : "l"(a), "l"(b), "l"(c));
    return d;
}
__device__ __forceinline__ float2 unpack2(ULL v) {
    unsigned lo, hi;
    asm("mov.b64 {%0, %1}, %2;" : "=r"(lo), "=r"(hi) : "l"(v));
    return make_float2(__uint_as_float(lo), __uint_as_float(hi));
}

// ================= kernel 1: S = A @ A per (s, b) =================
// grid (52, 16, 2): blockIdx.x = jt*4 + pt, y = b, z = s.  256 threads.
// output tile 16j x 64p, thread = 1j x 4p.
__global__ __launch_bounds__(256) void square_kernel(
    const float* __restrict__ a0, const float* __restrict__ a1)
{
    __shared__ float As[16][16];
    __shared__ float Bs[16][64];
    const int tid = threadIdx.x;
    const int jt = blockIdx.x >> 2, pt = blockIdx.x & 3;
    const int b = blockIdx.y, s = blockIdx.z;
    const float* A = (s == 0 ? a0 : a1) + (size_t)b*KK;
    float* S = g_S + (size_t)(s*B_DIM + b)*KK;

    const int jl = tid >> 4, pg = tid & 15;
    const int j = jt*16 + jl;
    const int p0 = pt*64 + pg*4;

    float acc0 = 0.f, acc1 = 0.f, acc2 = 0.f, acc3 = 0.f;
    for (int kt = 0; kt < 13; ++kt) {
        const int kb = kt*16;
        {
            int rr = tid >> 4, cc = tid & 15;
            int jj = jt*16 + rr, kk = kb + cc;
            As[rr][cc] = (jj < K_DIM && kk < K_DIM) ? A[(size_t)jj*K_DIM + kk] : 0.f;
        }
        #pragma unroll
        for (int q = 0; q < 4; ++q) {
            int idx = tid + q*256;
            int rr = idx >> 6, cc = idx & 63;
            int kk = kb + rr, pp = pt*64 + cc;
            Bs[rr][cc] = (kk < K_DIM && pp < K_DIM) ? A[(size_t)kk*K_DIM + pp] : 0.f;
        }
        __syncthreads();
        #pragma unroll
        for (int k = 0; k < 16; ++k) {
            float a = As[jl][k];
            float4 bv = *(const float4*)&Bs[k][pg*4];
            acc0 += a*bv.x; acc1 += a*bv.y; acc2 += a*bv.z; acc3 += a*bv.w;
        }
        __syncthreads();
    }
    if (j < K_DIM) {
        float* Sp = S + (size_t)j*K_DIM + p0;
        if (p0 + 3 < K_DIM) { Sp[0]=acc0; Sp[1]=acc1; Sp[2]=acc2; Sp[3]=acc3; }
        else {
            if (p0     < K_DIM) Sp[0] = acc0;
            if (p0 + 1 < K_DIM) Sp[1] = acc1;
            if (p0 + 2 < K_DIM) Sp[2] = acc2;
        }
    }
}

// ================= kernel 2: diffuse  t_m[b,c,j,l] = sum_k M_m[j,k] x[b,c,k,l] =================
// grid (7 jt, 4 m, 16 b), 256 threads, 1 CTA/SM (136KB smem).
// smem: Msm transposed [207 k][36 pad] (j-tile 32), Xsm [2 c][207 k][64 l].
// thread tile: 8j (as 4 j-pairs, f32x2) x 2l; 2 c-groups of 128 threads.
__global__ __launch_bounds__(256, 1) void diffuse_kernel(
    const float* __restrict__ x, const float* __restrict__ a0,
    const float* __restrict__ a1)
{
    extern __shared__ float sm[];
    float* Msm = sm;                 // [207][36]
    float* Xsm = sm + K_DIM*36;      // [2][KL]
    const int tid = threadIdx.x;
    const int jt = blockIdx.x, m = blockIdx.y, b = blockIdx.z;
    const int j0 = jt * 32;

    const float* M =
        (m == 0) ? a0  + (size_t)b*KK :
        (m == 1) ? g_S + (size_t)b*KK :
        (m == 2) ? a1  + (size_t)b*KK :
                   g_S + (size_t)(B_DIM + b)*KK;

    // load M tile transposed: Msm[k][jl] = M[j0+jl][k], zero-fill out-of-range rows
    for (int e = tid; e < K_DIM*32; e += 256) {
        int jl = e / K_DIM;
        int k  = e - jl*K_DIM;
        int j  = j0 + jl;
        Msm[k*36 + jl] = (j < K_DIM) ? M[(size_t)j*K_DIM + k] : 0.f;
    }

    const int cg = tid >> 7;
    const int t  = tid & 127;
    const int lg = t & 31, jg = t >> 5;
    const int l0 = lg*2, jb = jg*8;

    const float* xb = x + (size_t)b*C_DIM*KL;
    float* tb = g_t + ((size_t)(m*B_DIM + b))*C_DIM*KL;

    for (int c2 = 0; c2 < 32; ++c2) {
        __syncthreads();
        const float4* src = (const float4*)(xb + (size_t)(2*c2)*KL);
        float4* dst = (float4*)Xsm;
        for (int v = tid; v < (2*KL)/4; v += 256) dst[v] = src[v];
        __syncthreads();

        ULL acc[4][2] = {};
        const float* Xc = Xsm + cg*KL + l0;
        const float* Mc = Msm + jb;
        #pragma unroll 3
        for (int k = 0; k < K_DIM; ++k) {
            ulonglong2 p0 = *(const ulonglong2*)(Mc + k*36);
            ulonglong2 p1 = *(const ulonglong2*)(Mc + k*36 + 4);
            float2 xv = *(const float2*)(Xc + k*64);
            ULL xa = pack2(xv.x), xb2 = pack2(xv.y);
            ULL mj[4] = {p0.x, p0.y, p1.x, p1.y};
            #pragma unroll
            for (int q = 0; q < 4; ++q) {
                acc[q][0] = fma2(mj[q], xa,  acc[q][0]);
                acc[q][1] = fma2(mj[q], xb2, acc[q][1]);
            }
        }

        const int c = 2*c2 + cg;
        float* out = tb + (size_t)c*KL + l0;
        #pragma unroll
        for (int q = 0; q < 4; ++q) {
            int j = j0 + jb + 2*q;
            float2 v0 = unpack2(acc[q][0]);   // (j, j+1) at column l0
            float2 v1 = unpack2(acc[q][1]);   // (j, j+1) at column l0+1
            if (j     < K_DIM) *(float2*)(out + (size_t)j*64)     = make_float2(v0.x, v1.x);
            if (j + 1 < K_DIM) *(float2*)(out + (size_t)(j+1)*64) = make_float2(v0.y, v1.y);
        }
    }
}

// ================= kernel 3: conv  y[b,o,kl] = sum_i W[o,i] H[b,i,kl] + bias[o] =================
// H channel blocks: [x | g_t m=0 | m=1 | m=2 | m=3].
// grid (207 kl-tiles of 64, 16 b), 256 threads, 2 CTAs/SM (103KB smem).
// smem: Ws transposed [320 i][68 pad], Hs double-buffered [2][32 i][64 kl].
// thread tile: 8o (4 o-pairs, f32x2) x 2kl.
__global__ __launch_bounds__(256, 2) void conv_kernel(
    const float* __restrict__ x, const float* __restrict__ W,
    const float* __restrict__ bias, float* __restrict__ y)
{
    extern __shared__ float sm[];
    float* Ws = sm;                   // [320][68]
    float* Hs = sm + CIN*68;          // [2][32*64]
    const int tid = threadIdx.x;
    const int b = blockIdx.y;
    const int kl0 = blockIdx.x * 64;

    for (int e = tid; e < CIN*C_DIM; e += 256) {
        int o = e / CIN, i = e - o*CIN;
        Ws[i*68 + o] = W[e];          // W is [o][i] row-major; read coalesced over i
    }

    const int lg = tid & 31, og = tid >> 5;
    const int kll = lg*2, o0 = og*8;

    ULL acc[4][2];
    #pragma unroll
    for (int q = 0; q < 4; ++q) {
        float2 bb = *(const float2*)&bias[o0 + 2*q];
        ULL bp = packxy(bb.x, bb.y);
        acc[q][0] = bp; acc[q][1] = bp;
    }

    const int r  = tid >> 4;          // 0..15
    const int c4 = (tid & 15) * 4;    // 0..60

    // reg-staged double-buffered H chunks of 32 i
    float4 st0, st1;
    {   // prologue: chunk 0 rows are all x (i = 0..31 < 64)
        st0 = *(const float4*)(x + ((size_t)(b*C_DIM + r     ))*KL + kl0 + c4);
        st1 = *(const float4*)(x + ((size_t)(b*C_DIM + 16 + r))*KL + kl0 + c4);
    }
    for (int ch = 0; ch < 10; ++ch) {
        float* Hb = Hs + (ch & 1) * 2048;
        *(float4*)&Hb[r*64 + c4]        = st0;
        *(float4*)&Hb[(16 + r)*64 + c4] = st1;
        __syncthreads();
        if (ch < 9) {
            int ib = (ch + 1) * 32;
            int i0 = ib + r, i1 = ib + 16 + r;
            const float* rp0 = (i0 < 64)
                ? x   + ((size_t)(b*C_DIM + i0))*KL
                : g_t + ((size_t)((((i0 - 64) >> 6)*B_DIM + b)*C_DIM + ((i0 - 64) & 63)))*KL;
            const float* rp1 = (i1 < 64)
                ? x   + ((size_t)(b*C_DIM + i1))*KL
                : g_t + ((size_t)((((i1 - 64) >> 6)*B_DIM + b)*C_DIM + ((i1 - 64) & 63)))*KL;
            st0 = *(const float4*)(rp0 + kl0 + c4);
            st1 = *(const float4*)(rp1 + kl0 + c4);
        }
        const float* Wc = Ws + ch*32*68 + o0;
        const float* Hc = Hb + kll;
        #pragma unroll 4
        for (int ii = 0; ii < 32; ++ii) {
            ulonglong2 w0 = *(const ulonglong2*)(Wc + ii*68);
            ulonglong2 w1 = *(const ulonglong2*)(Wc + ii*68 + 4);
            float2 hv = *(const float2*)(Hc + ii*64);
            ULL ha = pack2(hv.x), hb2 = pack2(hv.y);
            ULL wv[4] = {w0.x, w0.y, w1.x, w1.y};
            #pragma unroll
            for (int q = 0; q < 4; ++q) {
                acc[q][0] = fma2(wv[q], ha,  acc[q][0]);
                acc[q][1] = fma2(wv[q], hb2, acc[q][1]);
            }
        }
        __syncthreads();
    }

    float* yo = y + ((size_t)b*C_DIM)*KL + kl0 + kll;
    #pragma unroll
    for (int q = 0; q < 4; ++q) {
        float2 v0 = unpack2(acc[q][0]);   // (o, o+1) at kll
        float2 v1 = unpack2(acc[q][1]);   // (o, o+1) at kll+1
        int olo = o0 + 2*q;
        *(float2*)(yo + (size_t)olo*KL)     = make_float2(v0.x, v1.x);
        *(float2*)(yo + (size_t)(olo+1)*KL) = make_float2(v0.y, v1.y);
    }
}

// =============================================================================
extern "C" void kernel_launch(void* const* d_in, const int* in_sizes, int n_in,
                              void* d_out, int out_size) {
    const float* x    = (const float*)d_in[0];
    const float* a0   = (const float*)d_in[1];
    const float* a1   = (const float*)d_in[2];
    const float* W    = (const float*)d_in[3];
    const float* bias = (const float*)d_in[4];
    float* y = (float*)d_out;

    const int diffuse_smem = (K_DIM*36 + 2*KL) * 4;          // 135792
    const int conv_smem    = (CIN*68 + 2*32*64) * 4;          // 103424
    cudaFuncSetAttribute(diffuse_kernel, cudaFuncAttributeMaxDynamicSharedMemorySize, diffuse_smem);
    cudaFuncSetAttribute(conv_kernel,    cudaFuncAttributeMaxDynamicSharedMemorySize, conv_smem);

    square_kernel <<<dim3(52, 16, 2), 256>>>(a0, a1);
    diffuse_kernel<<<dim3(7, 4, 16),  256, diffuse_smem>>>(x, a0, a1);
    conv_kernel   <<<dim3(207, 16),   256, conv_smem>>>(x, W, bias, y);
}

// round 12
// speedup vs baseline: 3.1721x; 3.1721x over previous
#include <cuda_runtime.h>
#include <cuda_bf16.h>

typedef unsigned int u32;

#define B_DIM 16
#define C_DIM 64
#define K_DIM 207
#define L_DIM 64
#define KL (K_DIM*L_DIM)      /* 13248 */
#define KK (K_DIM*K_DIM)      /* 42849 */

// scratch (allocation-free rule: __device__ global)
// blocks: m=0: A0x, m=1: A0^2 x, m=2: A1x, m=3: A1^2 x
__device__ float g_t[(size_t)4*B_DIM*C_DIM*KL];

// ---------------------------------------------------------------- helpers
__device__ __forceinline__ u32 smem_u32(const void* p) {
    u32 a;
    asm("{ .reg .u64 t; cvta.to.shared.u64 t, %1; cvt.u32.u64 %0, t; }" : "=r"(a) : "l"(p));
    return a;
}
// pack {lo: v0, hi: v1} as bf16x2
__device__ __forceinline__ u32 cvt2bf(float v0, float v1) {
    u32 r; asm("cvt.rn.bf16x2.f32 %0, %1, %2;" : "=r"(r) : "f"(v1), "f"(v0)); return r;
}
__device__ __forceinline__ float bflo_f(u32 h){ return __uint_as_float(h << 16); }
__device__ __forceinline__ float bfhi_f(u32 h){ return __uint_as_float(h & 0xFFFF0000u); }

__device__ __forceinline__ void ldsm4(u32& r0,u32& r1,u32& r2,u32& r3, u32 a){
    asm volatile("ldmatrix.sync.aligned.m8n8.x4.shared.b16 {%0,%1,%2,%3}, [%4];"
        : "=r"(r0),"=r"(r1),"=r"(r2),"=r"(r3) : "r"(a) : "memory");
}
__device__ __forceinline__ void ldsm4t(u32& r0,u32& r1,u32& r2,u32& r3, u32 a){
    asm volatile("ldmatrix.sync.aligned.m8n8.x4.trans.shared.b16 {%0,%1,%2,%3}, [%4];"
        : "=r"(r0),"=r"(r1),"=r"(r2),"=r"(r3) : "r"(a) : "memory");
}
__device__ __forceinline__ void mma_bf(float* c, const u32* a, const u32* b){
    asm("mma.sync.aligned.m16n8k16.row.col.f32.bf16.bf16.f32 "
        "{%0,%1,%2,%3}, {%4,%5,%6,%7}, {%8,%9}, {%0,%1,%2,%3};"
        : "+f"(c[0]),"+f"(c[1]),"+f"(c[2]),"+f"(c[3])
        : "r"(a[0]),"r"(a[1]),"r"(a[2]),"r"(a[3]), "r"(b[0]),"r"(b[1]));
}

// ================= diffuse pass: t[dst_m][b][c][j][l] = sum_k M[j,k] src[c][k][l]
// pass 0: src = x, dst m = {0,2};  pass 1: src = g_t[m=2s], dst m = {1,3}
// CTA: D[128 j x 256 n] (n = 4 channels x 64 l), 8 warps of 64x64.
// smem (bytes): Ahi [128 j][72]  Alo +18432 | Bhi [64 k][264] @36864  Blo @70656
#define D_AHI 0
#define D_ALO 18432
#define D_BHI 36864
#define D_BLO 70656
#define D_SMEM 104448

__global__ __launch_bounds__(256, 1) void diffuse_mma(
    const float* __restrict__ x, const float* __restrict__ a0,
    const float* __restrict__ a1, int pass)
{
    extern __shared__ char sm[];
    const u32 sb = smem_u32(sm);
    const int tid = threadIdx.x, lane = tid & 31, wid = tid >> 5;
    const int ct = blockIdx.x & 15, jt = blockIdx.x >> 4;
    const int s = blockIdx.y, b = blockIdx.z;
    const int j0 = jt*128;
    const int warp_m = wid >> 2, warp_n = wid & 3;
    const int jm0 = warp_m*64, n0 = warp_n*64;

    const float* M = (s ? a1 : a0) + (size_t)b*KK;
    const float* srcb = pass
        ? g_t + ((size_t)((s*2)*B_DIM + b)*C_DIM + ct*4)*KL
        : x   + ((size_t)b*C_DIM + ct*4)*KL;

    float acc[4][8][4];
    #pragma unroll
    for (int i = 0; i < 4; ++i)
        #pragma unroll
        for (int j = 0; j < 8; ++j)
            #pragma unroll
            for (int q = 0; q < 4; ++q) acc[i][j][q] = 0.f;

    // per-thread ldmatrix sub-offsets
    const u32 a_row = (u32)((lane & 15)*144 + (lane >> 4)*16);
    const u32 b_row = (u32)((lane & 15)*528 + (lane >> 4)*16);

    #pragma unroll 1
    for (int chunk = 0; chunk < 4; ++chunk) {
        const int kc = chunk*64;
        const int nk = (chunk == 3) ? 1 : 4;
        __syncthreads();
        // ---- stage A [128 j][64 k] hi/lo (2 k per thread, packed u32)
        #pragma unroll
        for (int it = 0; it < 16; ++it) {
            int e = tid + it*256;                 // < 4096
            int j = e >> 5, k2 = (e & 31)*2;
            int jg = j0 + j, kg = kc + k2;
            float v0 = (jg < K_DIM && kg     < K_DIM) ? M[(size_t)jg*K_DIM + kg]     : 0.f;
            float v1 = (jg < K_DIM && kg + 1 < K_DIM) ? M[(size_t)jg*K_DIM + kg + 1] : 0.f;
            u32 h = cvt2bf(v0, v1);
            u32 l = cvt2bf(v0 - bflo_f(h), v1 - bfhi_f(h));
            *(u32*)(sm + D_AHI + j*144 + k2*2) = h;
            *(u32*)(sm + D_ALO + j*144 + k2*2) = l;
        }
        // ---- stage B [64 k][256 n] hi/lo (float4 over l, uint2 stores)
        #pragma unroll
        for (int it = 0; it < 16; ++it) {
            int e = tid + it*256;                 // < 4096
            int l4 = (e & 15)*4, k = (e >> 4) & 63, c = e >> 10;
            int kg = kc + k;
            float4 v = make_float4(0.f, 0.f, 0.f, 0.f);
            if (kg < K_DIM) v = *(const float4*)(srcb + (size_t)c*KL + (size_t)kg*64 + l4);
            u32 h01 = cvt2bf(v.x, v.y), h23 = cvt2bf(v.z, v.w);
            u32 l01 = cvt2bf(v.x - bflo_f(h01), v.y - bfhi_f(h01));
            u32 l23 = cvt2bf(v.z - bflo_f(h23), v.w - bfhi_f(h23));
            int n = c*64 + l4;
            *(uint2*)(sm + D_BHI + k*528 + n*2) = make_uint2(h01, h23);
            *(uint2*)(sm + D_BLO + k*528 + n*2) = make_uint2(l01, l23);
        }
        __syncthreads();
        // ---- mma: 3 split-products per k-step
        #pragma unroll 1
        for (int kst = 0; kst < nk; ++kst) {
            #pragma unroll
            for (int p = 0; p < 3; ++p) {
                const u32 aoff = (p == 2) ? D_ALO : D_AHI;
                const u32 boff = (p == 1) ? D_BLO : D_BHI;
                u32 afr[4][4];
                #pragma unroll
                for (int mi = 0; mi < 4; ++mi)
                    ldsm4(afr[mi][0], afr[mi][1], afr[mi][2], afr[mi][3],
                          sb + aoff + (u32)((jm0 + mi*16)*144 + kst*32) + a_row);
                u32 bfr[8][2];
                #pragma unroll
                for (int nj = 0; nj < 4; ++nj) {
                    u32 r0, r1, r2, r3;
                    ldsm4t(r0, r1, r2, r3,
                           sb + boff + (u32)(kst*16*528 + (n0 + nj*16)*2) + b_row);
                    bfr[nj*2][0] = r0; bfr[nj*2][1] = r1;
                    bfr[nj*2+1][0] = r2; bfr[nj*2+1][1] = r3;
                }
                #pragma unroll
                for (int mi = 0; mi < 4; ++mi)
                    #pragma unroll
                    for (int nt = 0; nt < 8; ++nt)
                        mma_bf(acc[mi][nt], afr[mi], bfr[nt]);
            }
        }
    }

    // ---- epilogue: direct fp32 stores (32B-sector aligned float2 pairs)
    const int dst_m = s*2 + pass;
    float* tb = g_t + ((size_t)(dst_m*B_DIM + b)*C_DIM + ct*4 + warp_n)*KL;
    #pragma unroll
    for (int mi = 0; mi < 4; ++mi) {
        int r0 = j0 + jm0 + mi*16 + (lane >> 2);
        #pragma unroll
        for (int nt = 0; nt < 8; ++nt) {
            int l = nt*8 + (lane & 3)*2;
            if (r0 < K_DIM)
                *(float2*)(tb + (size_t)r0*64 + l) = make_float2(acc[mi][nt][0], acc[mi][nt][1]);
            if (r0 + 8 < K_DIM)
                *(float2*)(tb + (size_t)(r0+8)*64 + l) = make_float2(acc[mi][nt][2], acc[mi][nt][3]);
        }
    }
}

// ================= conv: y[b][o][kl] = sum_i W[o,i] H[i][kl] + bias[o]
// H blocks of 64 i: [x | g_t m=0..3].  CTA: D[128 kl x 64 o], warp 32x32.
// smem: Ahi [64 k][136] @0  Alo @17408 | Bhi [64 o][72] @34816  Blo @44032 | bias @53248
#define C_AHI 0
#define C_ALO 17408
#define C_BHI 34816
#define C_BLO 44032
#define C_BIAS 53248
#define C_SMEM 53504

__global__ __launch_bounds__(256, 2) void conv_mma(
    const float* __restrict__ x, const float* __restrict__ W,
    const float* __restrict__ bias, float* __restrict__ y)
{
    extern __shared__ char sm[];
    const u32 sb = smem_u32(sm);
    const int tid = threadIdx.x, lane = tid & 31, wid = tid >> 5;
    const int b = blockIdx.y;
    const int kl0 = blockIdx.x * 128;
    const int warp_m = wid >> 1, warp_n = wid & 1;
    const int klrow0 = warp_m*32, o0 = warp_n*32;
    float* biass = (float*)(sm + C_BIAS);

    if (tid < 64) biass[tid] = bias[tid];

    float acc[2][4][4];
    #pragma unroll
    for (int i = 0; i < 2; ++i)
        #pragma unroll
        for (int j = 0; j < 4; ++j)
            #pragma unroll
            for (int q = 0; q < 4; ++q) acc[i][j][q] = 0.f;

    // per-thread ldmatrix sub-offsets
    const u32 at_row = (u32)(((lane & 7) + ((lane >> 4) & 1)*8)*272 + ((lane >> 3) & 1)*16);
    const u32 b_row  = (u32)((lane & 15)*144 + (lane >> 4)*16);

    #pragma unroll 1
    for (int ch = 0; ch < 5; ++ch) {
        const float* base = (ch == 0)
            ? x   + (size_t)b*C_DIM*KL
            : g_t + (size_t)((ch - 1)*B_DIM + b)*C_DIM*KL;
        __syncthreads();
        // ---- stage A transposed [64 k][128 kl] hi/lo (float4 over kl)
        #pragma unroll
        for (int it = 0; it < 8; ++it) {
            int e = tid + it*256;                 // < 2048
            int r4 = (e & 31)*4, k = e >> 5;
            float4 v = make_float4(0.f, 0.f, 0.f, 0.f);
            if (kl0 + r4 < KL) v = *(const float4*)(base + (size_t)k*KL + kl0 + r4);
            u32 h01 = cvt2bf(v.x, v.y), h23 = cvt2bf(v.z, v.w);
            u32 l01 = cvt2bf(v.x - bflo_f(h01), v.y - bfhi_f(h01));
            u32 l23 = cvt2bf(v.z - bflo_f(h23), v.w - bfhi_f(h23));
            *(uint2*)(sm + C_AHI + k*272 + r4*2) = make_uint2(h01, h23);
            *(uint2*)(sm + C_ALO + k*272 + r4*2) = make_uint2(l01, l23);
        }
        // ---- stage B (W slab) [64 o][64 k] hi/lo
        #pragma unroll
        for (int it = 0; it < 4; ++it) {
            int e = tid + it*256;                 // < 1024
            int k4 = (e & 15)*4, o = e >> 4;
            float4 v = *(const float4*)(W + (size_t)o*320 + ch*64 + k4);
            u32 h01 = cvt2bf(v.x, v.y), h23 = cvt2bf(v.z, v.w);
            u32 l01 = cvt2bf(v.x - bflo_f(h01), v.y - bfhi_f(h01));
            u32 l23 = cvt2bf(v.z - bflo_f(h23), v.w - bfhi_f(h23));
            *(uint2*)(sm + C_BHI + o*144 + k4*2) = make_uint2(h01, h23);
            *(uint2*)(sm + C_BLO + o*144 + k4*2) = make_uint2(l01, l23);
        }
        __syncthreads();
        // ---- mma
        #pragma unroll 1
        for (int kst = 0; kst < 4; ++kst) {
            #pragma unroll
            for (int p = 0; p < 3; ++p) {
                const u32 aoff = (p == 2) ? C_ALO : C_AHI;
                const u32 boff = (p == 1) ? C_BLO : C_BHI;
                u32 afr[2][4];
                #pragma unroll
                for (int mi = 0; mi < 2; ++mi)
                    ldsm4t(afr[mi][0], afr[mi][1], afr[mi][2], afr[mi][3],
                           sb + aoff + (u32)(kst*16*272 + (klrow0 + mi*16)*2) + at_row);
                u32 bfr[4][2];
                #pragma unroll
                for (int nj = 0; nj < 2; ++nj) {
                    u32 r0, r1, r2, r3;
                    ldsm4(r0, r1, r2, r3,
                          sb + boff + (u32)((o0 + nj*16)*144 + kst*32) + b_row);
                    bfr[nj*2][0] = r0; bfr[nj*2][1] = r2;   // non-trans x4 pairing
                    bfr[nj*2+1][0] = r1; bfr[nj*2+1][1] = r3;
                }
                #pragma unroll
                for (int mi = 0; mi < 2; ++mi)
                    #pragma unroll
                    for (int nt = 0; nt < 4; ++nt)
                        mma_bf(acc[mi][nt], afr[mi], bfr[nt]);
            }
        }
    }

    // ---- epilogue: + bias, store y[b][o][kl]
    float* yb = y + (size_t)b*C_DIM*KL;
    #pragma unroll
    for (int mi = 0; mi < 2; ++mi) {
        int kl_r = kl0 + klrow0 + mi*16 + (lane >> 2);
        #pragma unroll
        for (int ni = 0; ni < 4; ++ni) {
            int o = o0 + ni*8 + (lane & 3)*2;
            float b0 = biass[o], b1 = biass[o + 1];
            if (kl_r < KL) {
                yb[(size_t)o*KL + kl_r]       = acc[mi][ni][0] + b0;
                yb[(size_t)(o+1)*KL + kl_r]   = acc[mi][ni][1] + b1;
            }
            if (kl_r + 8 < KL) {
                yb[(size_t)o*KL + kl_r+8]     = acc[mi][ni][2] + b0;
                yb[(size_t)(o+1)*KL + kl_r+8] = acc[mi][ni][3] + b1;
            }
        }
    }
}

// =============================================================================
extern "C" void kernel_launch(void* const* d_in, const int* in_sizes, int n_in,
                              void* d_out, int out_size) {
    const float* x    = (const float*)d_in[0];
    const float* a0   = (const float*)d_in[1];
    const float* a1   = (const float*)d_in[2];
    const float* W    = (const float*)d_in[3];
    const float* bias = (const float*)d_in[4];
    float* y = (float*)d_out;

    cudaFuncSetAttribute(diffuse_mma, cudaFuncAttributeMaxDynamicSharedMemorySize, D_SMEM);
    cudaFuncSetAttribute(conv_mma,    cudaFuncAttributeMaxDynamicSharedMemorySize, C_SMEM);

    diffuse_mma<<<dim3(32, 2, 16), 256, D_SMEM>>>(x, a0, a1, 0);  // A0x, A1x
    diffuse_mma<<<dim3(32, 2, 16), 256, D_SMEM>>>(x, a0, a1, 1);  // A0^2 x, A1^2 x
    conv_mma   <<<dim3(104, 16),   256, C_SMEM>>>(x, W, bias, y);
}